// round 14
// baseline (speedup 1.0000x reference)
#include <cuda_runtime.h>
#include <cuda_fp16.h>
#include <math.h>
#include <stdint.h>

#define BB  8
#define DIM 128
#define CL  32
#define HH  256
#define WW  256

#define APITCH 136            // fp16 elems per row (pitch) of A / weight images
#define APB    (APITCH*2)     // 272 B rows: 17*16 -> ldmatrix-aligned, conflict-free

// ---------------- device scratch ----------------
// dwconv outputs: packed fp16 channel-pairs, laid out exactly as A-build consumes
__device__ uint32_t g_S0p[BB*16*65536];
__device__ uint32_t g_D1p[BB*16*16384];
__device__ uint32_t g_D2p[BB*16*4096];
__device__ uint32_t g_D3p[BB*16*1024];
// pooled activations (fp32, inputs to dwconv)
__device__ float g_P1[BB*CL*16384];
__device__ float g_T2[BB*CL*16384];
__device__ float g_T3[BB*CL*16384];
__device__ float g_P2[BB*CL*4096];
__device__ float g_P3[BB*CL*1024];

// weight images: shuffle-folded, single fp16, [N][APITCH]
__device__ __align__(16) __half g_W1[64*APITCH];
__device__ __align__(16) __half g_W2[96*APITCH];
__device__ __align__(16) __half g_W3[128*APITCH];

// ---------------- smem layout: A(128x272) + W1+W2+W3 = 110.5 KB -> 2 CTAs/SM ----------------
#define OFF_A   0
#define OFF_W1  34816
#define OFF_W2  52224
#define OFF_W3  78336
#define SMEM_REQ 113152

// ---------------- asm helpers ----------------
__device__ __forceinline__ uint32_t smem_u32(const void* p) {
    uint32_t a;
    asm("{ .reg .u64 t; cvta.to.shared.u64 t, %1; cvt.u32.u64 %0, t; }" : "=r"(a) : "l"(p));
    return a;
}
__device__ __forceinline__ void ldsm_x4(uint32_t r[4], uint32_t addr) {
    asm volatile("ldmatrix.sync.aligned.m8n8.x4.shared.b16 {%0,%1,%2,%3}, [%4];"
        : "=r"(r[0]), "=r"(r[1]), "=r"(r[2]), "=r"(r[3]) : "r"(addr));
}
__device__ __forceinline__ void mma16816h(float d[4], const uint32_t a[4], uint32_t b0, uint32_t b1) {
    asm volatile("mma.sync.aligned.m16n8k16.row.col.f32.f16.f16.f32 "
        "{%0,%1,%2,%3}, {%4,%5,%6,%7}, {%8,%9}, {%0,%1,%2,%3};"
        : "+f"(d[0]), "+f"(d[1]), "+f"(d[2]), "+f"(d[3])
        : "r"(a[0]), "r"(a[1]), "r"(a[2]), "r"(a[3]), "r"(b0), "r"(b1));
}
__device__ __forceinline__ void sts32(uint32_t addr, uint32_t v) {
    asm volatile("st.shared.b32 [%0], %1;" :: "r"(addr), "r"(v) : "memory");
}
__device__ __forceinline__ void sts128(uint32_t addr, uint4 v) {
    asm volatile("st.shared.v4.b32 [%0], {%1,%2,%3,%4};"
        :: "r"(addr), "r"(v.x), "r"(v.y), "r"(v.z), "r"(v.w) : "memory");
}
__device__ __forceinline__ uint16_t h16(float v) {
    return __half_as_ushort(__float2half(v));
}
__device__ __forceinline__ uint32_t pack2(uint16_t a, uint16_t b) {
    return (uint32_t)a | ((uint32_t)b << 16);
}

// fast exact-GELU: A&S 7.1.26 erf (abs err 1.5e-7, invisible vs 3.8e-4 quant error)
__device__ __forceinline__ float fgelu(float v) {
    float ax = fabsf(v) * 0.70710678118654752f;
    float t  = __frcp_rn(fmaf(0.3275911f, ax, 1.0f));
    float p  = fmaf(1.061405429f, t, -1.453152027f);
    p = fmaf(p, t, 1.421413741f);
    p = fmaf(p, t, -0.284496736f);
    p = fmaf(p, t, 0.254829592f);
    p = p * t;
    float e = __expf(-ax * ax);
    float erfa = fmaf(-p, e, 1.0f);
    float s = copysignf(erfa, v);
    return 0.5f * v * (1.0f + s);
}

// ---------------- weight prep: shuffle-fold + fp16 ----------------
__global__ void k_prep(const float* __restrict__ w1, const float* __restrict__ w2,
                       const float* __restrict__ w3)
{
    int t = blockIdx.x * blockDim.x + threadIdx.x;
    float w; __half *ph; int r, k;
    if (t < 64*64) {
        r = t >> 6; k = t & 63;
        w = w1[(r << 6) + ((k & 7) << 3) + (k >> 3)];
        ph = g_W1;
    } else if (t < 64*64 + 96*96) {
        int u = t - 64*64; r = u / 96; k = u % 96;
        w = w2[r*96 + (k % 12)*8 + k/12];
        ph = g_W2;
    } else if (t < 64*64 + 96*96 + 128*128) {
        int u = t - 64*64 - 96*96; r = u >> 7; k = u & 127;
        w = w3[(r << 7) + ((k & 15) << 3) + (k >> 4)];
        ph = g_W3;
    } else return;
    ph[r*APITCH + k] = __float2half(w);
}

// ---------------- pool pass 1: half-res 2x2 max of channels 32..127 of x ----------------
__global__ void k_poolh(const float* __restrict__ x)
{
    int idx = blockIdx.x * blockDim.x + threadIdx.x;
    if (idx >= BB*96*16384) return;
    int xo = idx & 127;
    int yo = (idx >> 7) & 127;
    int c  = (idx >> 14) % 96;
    int b  = idx / (16384*96);
    const float* p = x + (((size_t)b*DIM + 32 + c)*HH + (size_t)yo*2)*WW + (size_t)xo*2;
    float m = fmaxf(fmaxf(p[0], p[1]), fmaxf(p[WW], p[WW+1]));
    int o = ((b*CL + (c & 31)) << 14) + (yo << 7) + xo;
    if (c < 32)      g_P1[o] = m;
    else if (c < 64) g_T2[o] = m;
    else             g_T3[o] = m;
}

// ---------------- pool pass 2: P2 = pool2(T2) ----------------
__global__ void k_pool2b()
{
    int idx = blockIdx.x * blockDim.x + threadIdx.x;
    if (idx >= BB*CL*4096) return;
    int xo = idx & 63;
    int yo = (idx >> 6) & 63;
    int bc = idx >> 12;
    const float* p = g_T2 + ((size_t)bc << 14) + (size_t)(yo*2)*128 + xo*2;
    g_P2[idx] = fmaxf(fmaxf(p[0], p[1]), fmaxf(p[128], p[129]));
}

// ---------------- pool pass 3: P3 = pool4(T3) ----------------
__global__ void k_pool4c()
{
    int idx = blockIdx.x * blockDim.x + threadIdx.x;
    if (idx >= BB*CL*1024) return;
    int xo = idx & 31;
    int yo = (idx >> 5) & 31;
    int bc = idx >> 10;
    const float* p = g_T3 + ((size_t)bc << 14) + (size_t)(yo*4)*128 + xo*4;
    float m = -3.402823466e38f;
    #pragma unroll
    for (int dy = 0; dy < 4; dy++)
        #pragma unroll
        for (int dx = 0; dx < 4; dx++)
            m = fmaxf(m, p[dy*128 + dx]);
    g_P3[idx] = m;
}

// ---------------- depthwise 3x3, channel PAIRS, fp16-packed output ----------------
__device__ __forceinline__ void dwp(const float* __restrict__ in, uint32_t* __restrict__ out,
                                    const float* __restrict__ w_dw, const float* __restrict__ b_dw,
                                    int lvl, int S, bool from_x, int idx)
{
    int xx = idx % S;
    int yy = (idx / S) % S;
    int cp = (idx / (S*S)) % 16;
    int b  = idx / (S*S*16);
    int c0 = 2*cp;
    const float* ip0 = from_x ? in + ((size_t)b*DIM + lvl*CL + c0) * (size_t)(S*S)
                              : in + ((size_t)b*CL + c0) * (size_t)(S*S);
    const float* ip1 = ip0 + (size_t)(S*S);
    const float* wp0 = w_dw + (lvl*CL + c0) * 9;
    const float* wp1 = wp0 + 9;
    float a0 = b_dw[lvl*CL + c0];
    float a1 = b_dw[lvl*CL + c0 + 1];
    #pragma unroll
    for (int ky = 0; ky < 3; ky++) {
        int iy = yy + ky - 1;
        if ((unsigned)iy >= (unsigned)S) continue;
        #pragma unroll
        for (int kx = 0; kx < 3; kx++) {
            int ix = xx + kx - 1;
            if ((unsigned)ix >= (unsigned)S) continue;
            int o = iy*S + ix;
            a0 = fmaf(wp0[ky*3 + kx], ip0[o], a0);
            a1 = fmaf(wp1[ky*3 + kx], ip1[o], a1);
        }
    }
    out[idx] = pack2(h16(a0), h16(a1));
}
#define N_DW0 (BB*16*65536)
#define N_DW1 (BB*16*16384)
#define N_DW2 (BB*16*4096)
#define N_DW3 (BB*16*1024)
__global__ void k_dwall(const float* __restrict__ x, const float* __restrict__ w,
                        const float* __restrict__ b)
{
    int idx = blockIdx.x * blockDim.x + threadIdx.x;
    if (idx < N_DW0) { dwp(x, g_S0p, w, b, 0, 256, true, idx); return; }
    idx -= N_DW0;
    if (idx < N_DW1) { dwp(g_P1, g_D1p, w, b, 1, 128, false, idx); return; }
    idx -= N_DW1;
    if (idx < N_DW2) { dwp(g_P2, g_D2p, w, b, 2, 64, false, idx); return; }
    idx -= N_DW2;
    if (idx < N_DW3) { dwp(g_P3, g_D3p, w, b, 3, 32, false, idx); return; }
}

// ---------------- D -> A fragment conversion (register-local) ----------------
__device__ __forceinline__ void d2a(const float d[][4], int g0, const float* __restrict__ bias,
                                    int lane, uint32_t a[4])
{
    int c0 = 8*g0 + (lane & 3)*2;
    float b00 = __ldg(bias + c0),     b01 = __ldg(bias + c0 + 1);
    float b10 = __ldg(bias + c0 + 8), b11 = __ldg(bias + c0 + 9);
    a[0] = pack2(h16(d[g0][0] + b00),   h16(d[g0][1] + b01));
    a[1] = pack2(h16(d[g0][2] + b00),   h16(d[g0][3] + b01));
    a[2] = pack2(h16(d[g0+1][0] + b10), h16(d[g0+1][1] + b11));
    a[3] = pack2(h16(d[g0+1][2] + b10), h16(d[g0+1][3] + b11));
}

// ---------------- fused kernel: warp-local chain, 256 thr, 8 warps, 2 CTAs/SM ----------------
#define TPC 4
#define NTHR 256
__global__ __launch_bounds__(NTHR, 2)
void fused_mma(const float* __restrict__ x,
               const float* __restrict__ bf1, const float* __restrict__ bf2,
               const float* __restrict__ bf3, float* __restrict__ out)
{
    extern __shared__ __align__(16) unsigned char sm[];
    const uint32_t base = smem_u32(sm);
    const int tid = threadIdx.x;
    const int lane = tid & 31, wid = tid >> 5;   // wid 0..7, owns pixels [wid*16, +16)

    // ---- load all weight images into smem once per CTA (78 KB, L2-hot) ----
    {
        const __half* gs[3] = { g_W1, g_W2, g_W3 };
        const int off[3] = { OFF_W1, OFF_W2, OFF_W3 };
        const int sz[3]  = { 17408, 26112, 34816 };
        #pragma unroll
        for (int a = 0; a < 3; a++) {
            const uint4* s4 = (const uint4*)gs[a];
            for (int i = tid; i < sz[a]/16; i += NTHR)
                sts128(base + off[a] + i*16, s4[i]);
        }
    }

    // per-warp constant addresses
    const uint32_t Abase = base + OFF_A + (uint32_t)(wid*16 + (lane & 15))*APB + ((lane >> 4) << 4);
    const uint32_t wb_off = (uint32_t)((lane & 7) + ((lane >> 4) << 3))*APB + (((lane >> 3) & 1) << 4);
    const uint32_t W1a = base + OFF_W1 + wb_off;
    const uint32_t W2a = base + OFF_W2 + wb_off;
    const uint32_t W3a = base + OFF_W3 + wb_off;

    float acc[16][4];
    uint32_t areg[6][4];

    for (int t = 0; t < TPC; t++) {
        int tile = blockIdx.x * TPC + t;
        int b = tile >> 9;                // 512 tiles per image
        int rem = (tile & 511) * 128;     // pixel base (half an image row)

        // ---- build A (128 px x 64 fp16 channel-pairs): pure gather + sts32 ----
        for (int i = tid; i < 128*64; i += NTHR) {
            int chp = i >> 7, p = i & 127;
            int r = rem + p;
            int y = r >> 8, xx = r & 255;
            int lvl = chp >> 4, cp = chp & 15;
            uint32_t v;
            if (lvl == 0)      v = g_S0p[((b*16 + cp) << 16) + r];
            else if (lvl == 1) v = g_D1p[(b*16 + cp)*16384 + (y>>1)*128 + (xx>>1)];
            else if (lvl == 2) v = g_D2p[(b*16 + cp)*4096  + (y>>2)*64  + (xx>>2)];
            else               v = g_D3p[(b*16 + cp)*1024  + (y>>3)*32  + (xx>>3)];
            sts32(base + OFF_A + (uint32_t)p*APB + chp*4, v);
        }
        __syncthreads();   // S1: A ready (covers W load on first tile too)

        // ---- stage 1: res1(64) = W1 @ A[0:64]  (KT=4, NT=8) ----
        #pragma unroll
        for (int n = 0; n < 8; n++)
            #pragma unroll
            for (int i = 0; i < 4; i++) acc[n][i] = 0.0f;
        #pragma unroll
        for (int kt = 0; kt < 4; kt++) {
            uint32_t a[4];
            ldsm_x4(a, Abase + kt*32);
            #pragma unroll
            for (int n2 = 0; n2 < 4; n2++) {
                uint32_t f[4];
                ldsm_x4(f, W1a + (uint32_t)n2*(16*APB) + kt*32);
                mma16816h(acc[2*n2],   a, f[0], f[1]);
                mma16816h(acc[2*n2+1], a, f[2], f[3]);
            }
        }
        #pragma unroll
        for (int j = 0; j < 4; j++) d2a(acc, 2*j, bf1, lane, areg[j]);

        // ---- stage 2: res2(96) = W2 @ [res1; s2]  (KT=6, NT=12) ----
        #pragma unroll
        for (int n = 0; n < 12; n++)
            #pragma unroll
            for (int i = 0; i < 4; i++) acc[n][i] = 0.0f;
        #pragma unroll
        for (int kt = 0; kt < 6; kt++) {
            uint32_t a[4];
            if (kt < 4) { a[0]=areg[kt][0]; a[1]=areg[kt][1]; a[2]=areg[kt][2]; a[3]=areg[kt][3]; }
            else ldsm_x4(a, Abase + kt*32);
            #pragma unroll
            for (int n2 = 0; n2 < 6; n2++) {
                uint32_t f[4];
                ldsm_x4(f, W2a + (uint32_t)n2*(16*APB) + kt*32);
                mma16816h(acc[2*n2],   a, f[0], f[1]);
                mma16816h(acc[2*n2+1], a, f[2], f[3]);
            }
        }
        #pragma unroll
        for (int j = 0; j < 6; j++) d2a(acc, 2*j, bf2, lane, areg[j]);

        // ---- stage 3: res3(128) = W3 @ [res2; s3]  (KT=8, NT=16) ----
        #pragma unroll
        for (int n = 0; n < 16; n++)
            #pragma unroll
            for (int i = 0; i < 4; i++) acc[n][i] = 0.0f;
        #pragma unroll
        for (int kt = 0; kt < 8; kt++) {
            uint32_t a[4];
            if (kt < 6) { a[0]=areg[kt][0]; a[1]=areg[kt][1]; a[2]=areg[kt][2]; a[3]=areg[kt][3]; }
            else ldsm_x4(a, Abase + kt*32);
            #pragma unroll
            for (int n2 = 0; n2 < 8; n2++) {
                uint32_t f[4];
                ldsm_x4(f, W3a + (uint32_t)n2*(16*APB) + kt*32);
                mma16816h(acc[2*n2],   a, f[0], f[1]);
                mma16816h(acc[2*n2+1], a, f[2], f[3]);
            }
        }
        __syncthreads();   // S2: all A-region reads done; next tile may overwrite

        // ---- epilogue: fgelu(res3+b3)*x, direct sector-aligned global stores ----
        {
            const int p0 = wid*16 + (lane >> 2);
            #pragma unroll
            for (int nt = 0; nt < 16; nt++) {
                int c0 = nt*8 + (lane & 3)*2;
                float b0 = __ldg(&bf3[c0]), b1 = __ldg(&bf3[c0+1]);
                size_t g0i = ((size_t)(b*128 + c0) << 16) + rem;
                size_t g1i = g0i + 65536;
                #pragma unroll
                for (int hrow = 0; hrow < 2; hrow++) {
                    int p = p0 + hrow*8;
                    float e0 = fgelu(acc[nt][2*hrow+0] + b0);
                    float e1 = fgelu(acc[nt][2*hrow+1] + b1);
                    out[g0i + p] = e0 * __ldg(&x[g0i + p]);
                    out[g1i + p] = e1 * __ldg(&x[g1i + p]);
                }
            }
        }
    }
}

// ---------------- launch ----------------
extern "C" void kernel_launch(void* const* d_in, const int* in_sizes, int n_in,
                              void* d_out, int out_size)
{
    const float* x   = (const float*)d_in[0];
    const float* wdw = (const float*)d_in[1];
    const float* bdw = (const float*)d_in[2];
    const float* wf1 = (const float*)d_in[3];
    const float* bf1 = (const float*)d_in[4];
    const float* wf2 = (const float*)d_in[5];
    const float* bf2 = (const float*)d_in[6];
    const float* wf3 = (const float*)d_in[7];
    const float* bf3 = (const float*)d_in[8];
    float* out = (float*)d_out;
    (void)in_sizes; (void)n_in; (void)out_size;

    cudaFuncSetAttribute(fused_mma, cudaFuncAttributeMaxDynamicSharedMemorySize, SMEM_REQ);

    k_prep<<<(64*64 + 96*96 + 128*128 + 255)/256, 256>>>(wf1, wf2, wf3);      // 0
    k_poolh<<<(BB*96*16384 + 255)/256, 256>>>(x);                              // 1
    k_pool2b<<<(BB*CL*4096 + 255)/256, 256>>>();                               // 2
    k_pool4c<<<(BB*CL*1024 + 255)/256, 256>>>();                               // 3
    k_dwall<<<(N_DW0+N_DW1+N_DW2+N_DW3 + 255)/256, 256>>>(x, wdw, bdw);        // 4
    fused_mma<<<1024, NTHR, SMEM_REQ>>>(x, bf1, bf2, bf3, out);                // 5
}

// round 15
// speedup vs baseline: 1.4116x; 1.4116x over previous
#include <cuda_runtime.h>
#include <cuda_fp16.h>
#include <math.h>
#include <stdint.h>

#define BB  8
#define DIM 128
#define CL  32
#define HH  256
#define WW  256

#define APITCH 136            // fp16 elems per row (pitch) of A / weight images
#define APB    (APITCH*2)     // 272 B rows: 17*16 -> ldmatrix-aligned, conflict-free

// ---------------- device scratch ----------------
__device__ uint32_t g_S0p[BB*16*65536];
__device__ uint32_t g_D1p[BB*16*16384];
__device__ uint32_t g_D2p[BB*16*4096];
__device__ uint32_t g_D3p[BB*16*1024];
__device__ float g_P1[BB*CL*16384];
__device__ float g_T2[BB*CL*16384];
__device__ float g_T3[BB*CL*16384];
__device__ float g_P2[BB*CL*4096];
__device__ float g_P3[BB*CL*1024];

__device__ __align__(16) __half g_W1[64*APITCH];
__device__ __align__(16) __half g_W2[96*APITCH];
__device__ __align__(16) __half g_W3[128*APITCH];

// ---------------- smem layout: A(128x272) + W1+W2+W3 = 110.5 KB -> 2 CTAs/SM ----------------
#define OFF_A   0
#define OFF_W1  34816
#define OFF_W2  52224
#define OFF_W3  78336
#define SMEM_REQ 113152

// ---------------- asm helpers ----------------
__device__ __forceinline__ uint32_t smem_u32(const void* p) {
    uint32_t a;
    asm("{ .reg .u64 t; cvta.to.shared.u64 t, %1; cvt.u32.u64 %0, t; }" : "=r"(a) : "l"(p));
    return a;
}
__device__ __forceinline__ void ldsm_x4(uint32_t r[4], uint32_t addr) {
    asm volatile("ldmatrix.sync.aligned.m8n8.x4.shared.b16 {%0,%1,%2,%3}, [%4];"
        : "=r"(r[0]), "=r"(r[1]), "=r"(r[2]), "=r"(r[3]) : "r"(addr));
}
__device__ __forceinline__ void mma16816h(float d[4], const uint32_t a[4], uint32_t b0, uint32_t b1) {
    asm volatile("mma.sync.aligned.m16n8k16.row.col.f32.f16.f16.f32 "
        "{%0,%1,%2,%3}, {%4,%5,%6,%7}, {%8,%9}, {%0,%1,%2,%3};"
        : "+f"(d[0]), "+f"(d[1]), "+f"(d[2]), "+f"(d[3])
        : "r"(a[0]), "r"(a[1]), "r"(a[2]), "r"(a[3]), "r"(b0), "r"(b1));
}
__device__ __forceinline__ void sts32(uint32_t addr, uint32_t v) {
    asm volatile("st.shared.b32 [%0], %1;" :: "r"(addr), "r"(v) : "memory");
}
__device__ __forceinline__ void sts128(uint32_t addr, uint4 v) {
    asm volatile("st.shared.v4.b32 [%0], {%1,%2,%3,%4};"
        :: "r"(addr), "r"(v.x), "r"(v.y), "r"(v.z), "r"(v.w) : "memory");
}
__device__ __forceinline__ uint16_t h16(float v) {
    return __half_as_ushort(__float2half(v));
}
__device__ __forceinline__ uint32_t pack2(uint16_t a, uint16_t b) {
    return (uint32_t)a | ((uint32_t)b << 16);
}

// minimal branchless exact-GELU: A&S 7.1.26 erf with raw MUFU rcp/ex2.
// abs err ~1.5e-7 -- invisible against the 3.8e-4 fp16 quantization error.
__device__ __forceinline__ float fgelu(float v) {
    float ax = fabsf(v) * 0.70710678118654752f;
    float w  = fmaf(0.3275911f, ax, 1.0f);
    float t;
    asm("rcp.approx.f32 %0, %1;" : "=f"(t) : "f"(w));
    float p = fmaf(1.061405429f, t, -1.453152027f);
    p = fmaf(p, t, 1.421413741f);
    p = fmaf(p, t, -0.284496736f);
    p = fmaf(p, t, 0.254829592f);
    p = p * t;
    float e;
    asm("ex2.approx.f32 %0, %1;" : "=f"(e) : "f"(ax * ax * -1.4426950408889634f));
    float erfa = fmaf(-p, e, 1.0f);                       // erf(|v|/sqrt2), >= 0
    uint32_t se = __float_as_uint(erfa) | (__float_as_uint(v) & 0x80000000u);
    float h = 0.5f * v;
    return fmaf(h, __uint_as_float(se), h);               // 0.5*v*(1+erf)
}

// ---------------- weight prep: shuffle-fold + fp16 ----------------
__global__ void k_prep(const float* __restrict__ w1, const float* __restrict__ w2,
                       const float* __restrict__ w3)
{
    int t = blockIdx.x * blockDim.x + threadIdx.x;
    float w; __half *ph; int r, k;
    if (t < 64*64) {
        r = t >> 6; k = t & 63;
        w = w1[(r << 6) + ((k & 7) << 3) + (k >> 3)];
        ph = g_W1;
    } else if (t < 64*64 + 96*96) {
        int u = t - 64*64; r = u / 96; k = u % 96;
        w = w2[r*96 + (k % 12)*8 + k/12];
        ph = g_W2;
    } else if (t < 64*64 + 96*96 + 128*128) {
        int u = t - 64*64 - 96*96; r = u >> 7; k = u & 127;
        w = w3[(r << 7) + ((k & 15) << 3) + (k >> 4)];
        ph = g_W3;
    } else return;
    ph[r*APITCH + k] = __float2half(w);
}

// ---------------- pool pass 1: half-res 2x2 max of channels 32..127 of x ----------------
__global__ void k_poolh(const float* __restrict__ x)
{
    int idx = blockIdx.x * blockDim.x + threadIdx.x;
    if (idx >= BB*96*16384) return;
    int xo = idx & 127;
    int yo = (idx >> 7) & 127;
    int c  = (idx >> 14) % 96;
    int b  = idx / (16384*96);
    const float* p = x + (((size_t)b*DIM + 32 + c)*HH + (size_t)yo*2)*WW + (size_t)xo*2;
    float m = fmaxf(fmaxf(p[0], p[1]), fmaxf(p[WW], p[WW+1]));
    int o = ((b*CL + (c & 31)) << 14) + (yo << 7) + xo;
    if (c < 32)      g_P1[o] = m;
    else if (c < 64) g_T2[o] = m;
    else             g_T3[o] = m;
}

// ---------------- pool pass 2: P2 = pool2(T2) ----------------
__global__ void k_pool2b()
{
    int idx = blockIdx.x * blockDim.x + threadIdx.x;
    if (idx >= BB*CL*4096) return;
    int xo = idx & 63;
    int yo = (idx >> 6) & 63;
    int bc = idx >> 12;
    const float* p = g_T2 + ((size_t)bc << 14) + (size_t)(yo*2)*128 + xo*2;
    g_P2[idx] = fmaxf(fmaxf(p[0], p[1]), fmaxf(p[128], p[129]));
}

// ---------------- pool pass 3: P3 = pool4(T3) ----------------
__global__ void k_pool4c()
{
    int idx = blockIdx.x * blockDim.x + threadIdx.x;
    if (idx >= BB*CL*1024) return;
    int xo = idx & 31;
    int yo = (idx >> 5) & 31;
    int bc = idx >> 10;
    const float* p = g_T3 + ((size_t)bc << 14) + (size_t)(yo*4)*128 + xo*4;
    float m = -3.402823466e38f;
    #pragma unroll
    for (int dy = 0; dy < 4; dy++)
        #pragma unroll
        for (int dx = 0; dx < 4; dx++)
            m = fmaxf(m, p[dy*128 + dx]);
    g_P3[idx] = m;
}

// ---------------- depthwise 3x3, channel PAIRS, fp16-packed output ----------------
__device__ __forceinline__ void dwp(const float* __restrict__ in, uint32_t* __restrict__ out,
                                    const float* __restrict__ w_dw, const float* __restrict__ b_dw,
                                    int lvl, int S, bool from_x, int idx)
{
    int xx = idx % S;
    int yy = (idx / S) % S;
    int cp = (idx / (S*S)) % 16;
    int b  = idx / (S*S*16);
    int c0 = 2*cp;
    const float* ip0 = from_x ? in + ((size_t)b*DIM + lvl*CL + c0) * (size_t)(S*S)
                              : in + ((size_t)b*CL + c0) * (size_t)(S*S);
    const float* ip1 = ip0 + (size_t)(S*S);
    const float* wp0 = w_dw + (lvl*CL + c0) * 9;
    const float* wp1 = wp0 + 9;
    float a0 = b_dw[lvl*CL + c0];
    float a1 = b_dw[lvl*CL + c0 + 1];
    #pragma unroll
    for (int ky = 0; ky < 3; ky++) {
        int iy = yy + ky - 1;
        if ((unsigned)iy >= (unsigned)S) continue;
        #pragma unroll
        for (int kx = 0; kx < 3; kx++) {
            int ix = xx + kx - 1;
            if ((unsigned)ix >= (unsigned)S) continue;
            int o = iy*S + ix;
            a0 = fmaf(wp0[ky*3 + kx], ip0[o], a0);
            a1 = fmaf(wp1[ky*3 + kx], ip1[o], a1);
        }
    }
    out[idx] = pack2(h16(a0), h16(a1));
}
#define N_DW0 (BB*16*65536)
#define N_DW1 (BB*16*16384)
#define N_DW2 (BB*16*4096)
#define N_DW3 (BB*16*1024)
__global__ void k_dwall(const float* __restrict__ x, const float* __restrict__ w,
                        const float* __restrict__ b)
{
    int idx = blockIdx.x * blockDim.x + threadIdx.x;
    if (idx < N_DW0) { dwp(x, g_S0p, w, b, 0, 256, true, idx); return; }
    idx -= N_DW0;
    if (idx < N_DW1) { dwp(g_P1, g_D1p, w, b, 1, 128, false, idx); return; }
    idx -= N_DW1;
    if (idx < N_DW2) { dwp(g_P2, g_D2p, w, b, 2, 64, false, idx); return; }
    idx -= N_DW2;
    if (idx < N_DW3) { dwp(g_P3, g_D3p, w, b, 3, 32, false, idx); return; }
}

// ---------------- D -> A fragment conversion (register-local) ----------------
__device__ __forceinline__ void d2a(const float d[][4], int g0, const float* __restrict__ bias,
                                    int lane, uint32_t a[4])
{
    int c0 = 8*g0 + (lane & 3)*2;
    float b00 = __ldg(bias + c0),     b01 = __ldg(bias + c0 + 1);
    float b10 = __ldg(bias + c0 + 8), b11 = __ldg(bias + c0 + 9);
    a[0] = pack2(h16(d[g0][0] + b00),   h16(d[g0][1] + b01));
    a[1] = pack2(h16(d[g0][2] + b00),   h16(d[g0][3] + b01));
    a[2] = pack2(h16(d[g0+1][0] + b10), h16(d[g0+1][1] + b11));
    a[3] = pack2(h16(d[g0+1][2] + b10), h16(d[g0+1][3] + b11));
}

// ---------------- fused kernel: warp-local chain, 256 thr, 8 warps, 2 CTAs/SM ----------------
#define TPC 4
#define NTHR 256
__global__ __launch_bounds__(NTHR, 2)
void fused_mma(const float* __restrict__ x,
               const float* __restrict__ bf1, const float* __restrict__ bf2,
               const float* __restrict__ bf3, float* __restrict__ out)
{
    extern __shared__ __align__(16) unsigned char sm[];
    const uint32_t base = smem_u32(sm);
    const int tid = threadIdx.x;
    const int lane = tid & 31, wid = tid >> 5;   // wid 0..7, owns pixels [wid*16, +16)

    // ---- load all weight images into smem once per CTA (78 KB, L2-hot) ----
    {
        const __half* gs[3] = { g_W1, g_W2, g_W3 };
        const int off[3] = { OFF_W1, OFF_W2, OFF_W3 };
        const int sz[3]  = { 17408, 26112, 34816 };
        #pragma unroll
        for (int a = 0; a < 3; a++) {
            const uint4* s4 = (const uint4*)gs[a];
            for (int i = tid; i < sz[a]/16; i += NTHR)
                sts128(base + off[a] + i*16, s4[i]);
        }
    }

    // per-warp constant addresses
    const uint32_t Abase = base + OFF_A + (uint32_t)(wid*16 + (lane & 15))*APB + ((lane >> 4) << 4);
    const uint32_t wb_off = (uint32_t)((lane & 7) + ((lane >> 4) << 3))*APB + (((lane >> 3) & 1) << 4);
    const uint32_t W1a = base + OFF_W1 + wb_off;
    const uint32_t W2a = base + OFF_W2 + wb_off;
    const uint32_t W3a = base + OFF_W3 + wb_off;

    float acc[16][4];
    uint32_t areg[6][4];

    for (int t = 0; t < TPC; t++) {
        int tile = blockIdx.x * TPC + t;
        int b = tile >> 9;                // 512 tiles per image
        int rem = (tile & 511) * 128;     // pixel base (half an image row)

        // ---- build A (128 px x 64 fp16 channel-pairs): pure gather + sts32 ----
        for (int i = tid; i < 128*64; i += NTHR) {
            int chp = i >> 7, p = i & 127;
            int r = rem + p;
            int y = r >> 8, xx = r & 255;
            int lvl = chp >> 4, cp = chp & 15;
            uint32_t v;
            if (lvl == 0)      v = g_S0p[((b*16 + cp) << 16) + r];
            else if (lvl == 1) v = g_D1p[(b*16 + cp)*16384 + (y>>1)*128 + (xx>>1)];
            else if (lvl == 2) v = g_D2p[(b*16 + cp)*4096  + (y>>2)*64  + (xx>>2)];
            else               v = g_D3p[(b*16 + cp)*1024  + (y>>3)*32  + (xx>>3)];
            sts32(base + OFF_A + (uint32_t)p*APB + chp*4, v);
        }
        __syncthreads();   // S1: A ready (covers W load on first tile too)

        // ---- stage 1: res1(64) = W1 @ A[0:64]  (KT=4, NT=8) ----
        #pragma unroll
        for (int n = 0; n < 8; n++)
            #pragma unroll
            for (int i = 0; i < 4; i++) acc[n][i] = 0.0f;
        #pragma unroll
        for (int kt = 0; kt < 4; kt++) {
            uint32_t a[4];
            ldsm_x4(a, Abase + kt*32);
            #pragma unroll
            for (int n2 = 0; n2 < 4; n2++) {
                uint32_t f[4];
                ldsm_x4(f, W1a + (uint32_t)n2*(16*APB) + kt*32);
                mma16816h(acc[2*n2],   a, f[0], f[1]);
                mma16816h(acc[2*n2+1], a, f[2], f[3]);
            }
        }
        #pragma unroll
        for (int j = 0; j < 4; j++) d2a(acc, 2*j, bf1, lane, areg[j]);

        // ---- stage 2: res2(96) = W2 @ [res1; s2]  (KT=6, NT=12) ----
        #pragma unroll
        for (int n = 0; n < 12; n++)
            #pragma unroll
            for (int i = 0; i < 4; i++) acc[n][i] = 0.0f;
        #pragma unroll
        for (int kt = 0; kt < 6; kt++) {
            uint32_t a[4];
            if (kt < 4) { a[0]=areg[kt][0]; a[1]=areg[kt][1]; a[2]=areg[kt][2]; a[3]=areg[kt][3]; }
            else ldsm_x4(a, Abase + kt*32);
            #pragma unroll
            for (int n2 = 0; n2 < 6; n2++) {
                uint32_t f[4];
                ldsm_x4(f, W2a + (uint32_t)n2*(16*APB) + kt*32);
                mma16816h(acc[2*n2],   a, f[0], f[1]);
                mma16816h(acc[2*n2+1], a, f[2], f[3]);
            }
        }
        #pragma unroll
        for (int j = 0; j < 6; j++) d2a(acc, 2*j, bf2, lane, areg[j]);

        // ---- stage 3: res3(128) = W3 @ [res2; s3]  (KT=8, NT=16) ----
        #pragma unroll
        for (int n = 0; n < 16; n++)
            #pragma unroll
            for (int i = 0; i < 4; i++) acc[n][i] = 0.0f;
        #pragma unroll
        for (int kt = 0; kt < 8; kt++) {
            uint32_t a[4];
            if (kt < 6) { a[0]=areg[kt][0]; a[1]=areg[kt][1]; a[2]=areg[kt][2]; a[3]=areg[kt][3]; }
            else ldsm_x4(a, Abase + kt*32);
            #pragma unroll
            for (int n2 = 0; n2 < 8; n2++) {
                uint32_t f[4];
                ldsm_x4(f, W3a + (uint32_t)n2*(16*APB) + kt*32);
                mma16816h(acc[2*n2],   a, f[0], f[1]);
                mma16816h(acc[2*n2+1], a, f[2], f[3]);
            }
        }
        __syncthreads();   // S2: all A-region reads done; next tile may overwrite

        // ---- epilogue: fgelu(res3+b3)*x, direct sector-aligned global stores ----
        {
            const int p0 = wid*16 + (lane >> 2);
            #pragma unroll
            for (int nt = 0; nt < 16; nt++) {
                int c0 = nt*8 + (lane & 3)*2;
                float b0 = __ldg(&bf3[c0]), b1 = __ldg(&bf3[c0+1]);
                size_t g0i = ((size_t)(b*128 + c0) << 16) + rem;
                size_t g1i = g0i + 65536;
                #pragma unroll
                for (int hrow = 0; hrow < 2; hrow++) {
                    int p = p0 + hrow*8;
                    float e0 = fgelu(acc[nt][2*hrow+0] + b0);
                    float e1 = fgelu(acc[nt][2*hrow+1] + b1);
                    out[g0i + p] = e0 * __ldg(&x[g0i + p]);
                    out[g1i + p] = e1 * __ldg(&x[g1i + p]);
                }
            }
        }
    }
}

// ---------------- launch ----------------
extern "C" void kernel_launch(void* const* d_in, const int* in_sizes, int n_in,
                              void* d_out, int out_size)
{
    const float* x   = (const float*)d_in[0];
    const float* wdw = (const float*)d_in[1];
    const float* bdw = (const float*)d_in[2];
    const float* wf1 = (const float*)d_in[3];
    const float* bf1 = (const float*)d_in[4];
    const float* wf2 = (const float*)d_in[5];
    const float* bf2 = (const float*)d_in[6];
    const float* wf3 = (const float*)d_in[7];
    const float* bf3 = (const float*)d_in[8];
    float* out = (float*)d_out;
    (void)in_sizes; (void)n_in; (void)out_size;

    cudaFuncSetAttribute(fused_mma, cudaFuncAttributeMaxDynamicSharedMemorySize, SMEM_REQ);

    k_prep<<<(64*64 + 96*96 + 128*128 + 255)/256, 256>>>(wf1, wf2, wf3);      // 0
    k_poolh<<<(BB*96*16384 + 255)/256, 256>>>(x);                              // 1
    k_pool2b<<<(BB*CL*4096 + 255)/256, 256>>>();                               // 2
    k_pool4c<<<(BB*CL*1024 + 255)/256, 256>>>();                               // 3
    k_dwall<<<(N_DW0+N_DW1+N_DW2+N_DW3 + 255)/256, 256>>>(x, wdw, bdw);        // 4
    fused_mma<<<1024, NTHR, SMEM_REQ>>>(x, bf1, bf2, bf3, out);                // 5
}

// round 16
// speedup vs baseline: 1.4539x; 1.0300x over previous
#include <cuda_runtime.h>
#include <cuda_fp16.h>
#include <math.h>
#include <stdint.h>

#define BB  8
#define DIM 128
#define CL  32
#define HH  256
#define WW  256

#define APITCH 136            // fp16 elems per row (pitch) of A / weight images
#define APB    (APITCH*2)     // 272 B rows: 17*16 -> ldmatrix-aligned, conflict-free

// ---------------- device scratch ----------------
__device__ uint32_t g_S0p[BB*16*65536];
__device__ uint32_t g_D1p[BB*16*16384];
__device__ uint32_t g_D2p[BB*16*4096];
__device__ uint32_t g_D3p[BB*16*1024];
__device__ float g_P1[BB*CL*16384];
__device__ float g_T2[BB*CL*16384];
__device__ float g_T3[BB*CL*16384];
__device__ float g_P2[BB*CL*4096];
__device__ float g_P3[BB*CL*1024];

__device__ __align__(16) __half g_W1[64*APITCH];
__device__ __align__(16) __half g_W2[96*APITCH];
__device__ __align__(16) __half g_W3[128*APITCH];

// ---------------- smem layout: A(128x272) + W1+W2+W3 = 110.5 KB -> 2 CTAs/SM ----------------
#define OFF_A   0
#define OFF_W1  34816
#define OFF_W2  52224
#define OFF_W3  78336
#define SMEM_REQ 113152

// ---------------- asm helpers ----------------
__device__ __forceinline__ uint32_t smem_u32(const void* p) {
    uint32_t a;
    asm("{ .reg .u64 t; cvta.to.shared.u64 t, %1; cvt.u32.u64 %0, t; }" : "=r"(a) : "l"(p));
    return a;
}
__device__ __forceinline__ void ldsm_x4(uint32_t r[4], uint32_t addr) {
    asm volatile("ldmatrix.sync.aligned.m8n8.x4.shared.b16 {%0,%1,%2,%3}, [%4];"
        : "=r"(r[0]), "=r"(r[1]), "=r"(r[2]), "=r"(r[3]) : "r"(addr));
}
__device__ __forceinline__ void mma16816h(float d[4], const uint32_t a[4], uint32_t b0, uint32_t b1) {
    asm volatile("mma.sync.aligned.m16n8k16.row.col.f32.f16.f16.f32 "
        "{%0,%1,%2,%3}, {%4,%5,%6,%7}, {%8,%9}, {%0,%1,%2,%3};"
        : "+f"(d[0]), "+f"(d[1]), "+f"(d[2]), "+f"(d[3])
        : "r"(a[0]), "r"(a[1]), "r"(a[2]), "r"(a[3]), "r"(b0), "r"(b1));
}
__device__ __forceinline__ void sts32(uint32_t addr, uint32_t v) {
    asm volatile("st.shared.b32 [%0], %1;" :: "r"(addr), "r"(v) : "memory");
}
__device__ __forceinline__ void sts128(uint32_t addr, uint4 v) {
    asm volatile("st.shared.v4.b32 [%0], {%1,%2,%3,%4};"
        :: "r"(addr), "r"(v.x), "r"(v.y), "r"(v.z), "r"(v.w) : "memory");
}
__device__ __forceinline__ uint16_t h16(float v) {
    return __half_as_ushort(__float2half(v));
}
__device__ __forceinline__ uint32_t pack2(uint16_t a, uint16_t b) {
    return (uint32_t)a | ((uint32_t)b << 16);
}

// minimal branchless exact-GELU: A&S 7.1.26 erf with raw MUFU rcp/ex2.
// abs err ~1.5e-7 -- invisible against the 3.8e-4 fp16 quantization error.
__device__ __forceinline__ float fgelu(float v) {
    float ax = fabsf(v) * 0.70710678118654752f;
    float w  = fmaf(0.3275911f, ax, 1.0f);
    float t;
    asm("rcp.approx.f32 %0, %1;" : "=f"(t) : "f"(w));
    float p = fmaf(1.061405429f, t, -1.453152027f);
    p = fmaf(p, t, 1.421413741f);
    p = fmaf(p, t, -0.284496736f);
    p = fmaf(p, t, 0.254829592f);
    p = p * t;
    float e;
    asm("ex2.approx.f32 %0, %1;" : "=f"(e) : "f"(ax * ax * -1.4426950408889634f));
    float erfa = fmaf(-p, e, 1.0f);                       // erf(|v|/sqrt2), >= 0
    uint32_t se = __float_as_uint(erfa) | (__float_as_uint(v) & 0x80000000u);
    float h = 0.5f * v;
    return fmaf(h, __uint_as_float(se), h);               // 0.5*v*(1+erf)
}

// ---------------- weight prep: shuffle-fold + fp16 ----------------
__global__ void k_prep(const float* __restrict__ w1, const float* __restrict__ w2,
                       const float* __restrict__ w3)
{
    int t = blockIdx.x * blockDim.x + threadIdx.x;
    float w; __half *ph; int r, k;
    if (t < 64*64) {
        r = t >> 6; k = t & 63;
        w = w1[(r << 6) + ((k & 7) << 3) + (k >> 3)];
        ph = g_W1;
    } else if (t < 64*64 + 96*96) {
        int u = t - 64*64; r = u / 96; k = u % 96;
        w = w2[r*96 + (k % 12)*8 + k/12];
        ph = g_W2;
    } else if (t < 64*64 + 96*96 + 128*128) {
        int u = t - 64*64 - 96*96; r = u >> 7; k = u & 127;
        w = w3[(r << 7) + ((k & 15) << 3) + (k >> 4)];
        ph = g_W3;
    } else return;
    ph[r*APITCH + k] = __float2half(w);
}

// ---------------- pool pass 1: half-res 2x2 max of channels 32..127 of x ----------------
__global__ void k_poolh(const float* __restrict__ x)
{
    int idx = blockIdx.x * blockDim.x + threadIdx.x;
    if (idx >= BB*96*16384) return;
    int xo = idx & 127;
    int yo = (idx >> 7) & 127;
    int c  = (idx >> 14) % 96;
    int b  = idx / (16384*96);
    const float* p = x + (((size_t)b*DIM + 32 + c)*HH + (size_t)yo*2)*WW + (size_t)xo*2;
    float m = fmaxf(fmaxf(p[0], p[1]), fmaxf(p[WW], p[WW+1]));
    int o = ((b*CL + (c & 31)) << 14) + (yo << 7) + xo;
    if (c < 32)      g_P1[o] = m;
    else if (c < 64) g_T2[o] = m;
    else             g_T3[o] = m;
}

// ---------------- pool pass 2: P2 = pool2(T2) ----------------
__global__ void k_pool2b()
{
    int idx = blockIdx.x * blockDim.x + threadIdx.x;
    if (idx >= BB*CL*4096) return;
    int xo = idx & 63;
    int yo = (idx >> 6) & 63;
    int bc = idx >> 12;
    const float* p = g_T2 + ((size_t)bc << 14) + (size_t)(yo*2)*128 + xo*2;
    g_P2[idx] = fmaxf(fmaxf(p[0], p[1]), fmaxf(p[128], p[129]));
}

// ---------------- pool pass 3: P3 = pool4(T3) ----------------
__global__ void k_pool4c()
{
    int idx = blockIdx.x * blockDim.x + threadIdx.x;
    if (idx >= BB*CL*1024) return;
    int xo = idx & 31;
    int yo = (idx >> 5) & 31;
    int bc = idx >> 10;
    const float* p = g_T3 + ((size_t)bc << 14) + (size_t)(yo*4)*128 + xo*4;
    float m = -3.402823466e38f;
    #pragma unroll
    for (int dy = 0; dy < 4; dy++)
        #pragma unroll
        for (int dx = 0; dx < 4; dx++)
            m = fmaxf(m, p[dy*128 + dx]);
    g_P3[idx] = m;
}

// ---------------- depthwise 3x3, channel PAIRS, fp16-packed output ----------------
__device__ __forceinline__ void dwp(const float* __restrict__ in, uint32_t* __restrict__ out,
                                    const float* __restrict__ w_dw, const float* __restrict__ b_dw,
                                    int lvl, int S, bool from_x, int idx)
{
    int xx = idx % S;
    int yy = (idx / S) % S;
    int cp = (idx / (S*S)) % 16;
    int b  = idx / (S*S*16);
    int c0 = 2*cp;
    const float* ip0 = from_x ? in + ((size_t)b*DIM + lvl*CL + c0) * (size_t)(S*S)
                              : in + ((size_t)b*CL + c0) * (size_t)(S*S);
    const float* ip1 = ip0 + (size_t)(S*S);
    const float* wp0 = w_dw + (lvl*CL + c0) * 9;
    const float* wp1 = wp0 + 9;
    float a0 = b_dw[lvl*CL + c0];
    float a1 = b_dw[lvl*CL + c0 + 1];
    #pragma unroll
    for (int ky = 0; ky < 3; ky++) {
        int iy = yy + ky - 1;
        if ((unsigned)iy >= (unsigned)S) continue;
        #pragma unroll
        for (int kx = 0; kx < 3; kx++) {
            int ix = xx + kx - 1;
            if ((unsigned)ix >= (unsigned)S) continue;
            int o = iy*S + ix;
            a0 = fmaf(wp0[ky*3 + kx], ip0[o], a0);
            a1 = fmaf(wp1[ky*3 + kx], ip1[o], a1);
        }
    }
    out[idx] = pack2(h16(a0), h16(a1));
}
#define N_DW0 (BB*16*65536)
#define N_DW1 (BB*16*16384)
#define N_DW2 (BB*16*4096)
#define N_DW3 (BB*16*1024)
__global__ void k_dwall(const float* __restrict__ x, const float* __restrict__ w,
                        const float* __restrict__ b)
{
    int idx = blockIdx.x * blockDim.x + threadIdx.x;
    if (idx < N_DW0) { dwp(x, g_S0p, w, b, 0, 256, true, idx); return; }
    idx -= N_DW0;
    if (idx < N_DW1) { dwp(g_P1, g_D1p, w, b, 1, 128, false, idx); return; }
    idx -= N_DW1;
    if (idx < N_DW2) { dwp(g_P2, g_D2p, w, b, 2, 64, false, idx); return; }
    idx -= N_DW2;
    if (idx < N_DW3) { dwp(g_P3, g_D3p, w, b, 3, 32, false, idx); return; }
}

// ---------------- D -> A fragment conversion (register-local) ----------------
__device__ __forceinline__ void d2a(const float d[][4], int g0, const float* __restrict__ bias,
                                    int lane, uint32_t a[4])
{
    int c0 = 8*g0 + (lane & 3)*2;
    float b00 = __ldg(bias + c0),     b01 = __ldg(bias + c0 + 1);
    float b10 = __ldg(bias + c0 + 8), b11 = __ldg(bias + c0 + 9);
    a[0] = pack2(h16(d[g0][0] + b00),   h16(d[g0][1] + b01));
    a[1] = pack2(h16(d[g0][2] + b00),   h16(d[g0][3] + b01));
    a[2] = pack2(h16(d[g0+1][0] + b10), h16(d[g0+1][1] + b11));
    a[3] = pack2(h16(d[g0+1][2] + b10), h16(d[g0+1][3] + b11));
}

// ---------------- fused kernel: warp-local chain, 256 thr, 8 warps, 2 CTAs/SM ----------------
// TPC=2 / grid=2048: halves CTA lifetime -> wave-quantization drain shrinks ~10x
#define TPC 2
#define NTHR 256
__global__ __launch_bounds__(NTHR, 2)
void fused_mma(const float* __restrict__ x,
               const float* __restrict__ bf1, const float* __restrict__ bf2,
               const float* __restrict__ bf3, float* __restrict__ out)
{
    extern __shared__ __align__(16) unsigned char sm[];
    const uint32_t base = smem_u32(sm);
    const int tid = threadIdx.x;
    const int lane = tid & 31, wid = tid >> 5;   // wid 0..7, owns pixels [wid*16, +16)

    // ---- load all weight images into smem once per CTA (78 KB, L2-hot) ----
    {
        const __half* gs[3] = { g_W1, g_W2, g_W3 };
        const int off[3] = { OFF_W1, OFF_W2, OFF_W3 };
        const int sz[3]  = { 17408, 26112, 34816 };
        #pragma unroll
        for (int a = 0; a < 3; a++) {
            const uint4* s4 = (const uint4*)gs[a];
            for (int i = tid; i < sz[a]/16; i += NTHR)
                sts128(base + off[a] + i*16, s4[i]);
        }
    }

    // per-warp constant addresses
    const uint32_t Abase = base + OFF_A + (uint32_t)(wid*16 + (lane & 15))*APB + ((lane >> 4) << 4);
    const uint32_t wb_off = (uint32_t)((lane & 7) + ((lane >> 4) << 3))*APB + (((lane >> 3) & 1) << 4);
    const uint32_t W1a = base + OFF_W1 + wb_off;
    const uint32_t W2a = base + OFF_W2 + wb_off;
    const uint32_t W3a = base + OFF_W3 + wb_off;

    float acc[16][4];
    uint32_t areg[6][4];

    for (int t = 0; t < TPC; t++) {
        int tile = blockIdx.x * TPC + t;
        int b = tile >> 9;                // 512 tiles per image
        int rem = (tile & 511) * 128;     // pixel base (half an image row)

        // ---- build A (128 px x 64 fp16 channel-pairs): pure gather + sts32 ----
        for (int i = tid; i < 128*64; i += NTHR) {
            int chp = i >> 7, p = i & 127;
            int r = rem + p;
            int y = r >> 8, xx = r & 255;
            int lvl = chp >> 4, cp = chp & 15;
            uint32_t v;
            if (lvl == 0)      v = g_S0p[((b*16 + cp) << 16) + r];
            else if (lvl == 1) v = g_D1p[(b*16 + cp)*16384 + (y>>1)*128 + (xx>>1)];
            else if (lvl == 2) v = g_D2p[(b*16 + cp)*4096  + (y>>2)*64  + (xx>>2)];
            else               v = g_D3p[(b*16 + cp)*1024  + (y>>3)*32  + (xx>>3)];
            sts32(base + OFF_A + (uint32_t)p*APB + chp*4, v);
        }
        __syncthreads();   // S1: A ready (covers W load on first tile too)

        // ---- stage 1: res1(64) = W1 @ A[0:64]  (KT=4, NT=8) ----
        #pragma unroll
        for (int n = 0; n < 8; n++)
            #pragma unroll
            for (int i = 0; i < 4; i++) acc[n][i] = 0.0f;
        #pragma unroll
        for (int kt = 0; kt < 4; kt++) {
            uint32_t a[4];
            ldsm_x4(a, Abase + kt*32);
            #pragma unroll
            for (int n2 = 0; n2 < 4; n2++) {
                uint32_t f[4];
                ldsm_x4(f, W1a + (uint32_t)n2*(16*APB) + kt*32);
                mma16816h(acc[2*n2],   a, f[0], f[1]);
                mma16816h(acc[2*n2+1], a, f[2], f[3]);
            }
        }
        #pragma unroll
        for (int j = 0; j < 4; j++) d2a(acc, 2*j, bf1, lane, areg[j]);

        // ---- stage 2: res2(96) = W2 @ [res1; s2]  (KT=6, NT=12) ----
        #pragma unroll
        for (int n = 0; n < 12; n++)
            #pragma unroll
            for (int i = 0; i < 4; i++) acc[n][i] = 0.0f;
        #pragma unroll
        for (int kt = 0; kt < 6; kt++) {
            uint32_t a[4];
            if (kt < 4) { a[0]=areg[kt][0]; a[1]=areg[kt][1]; a[2]=areg[kt][2]; a[3]=areg[kt][3]; }
            else ldsm_x4(a, Abase + kt*32);
            #pragma unroll
            for (int n2 = 0; n2 < 6; n2++) {
                uint32_t f[4];
                ldsm_x4(f, W2a + (uint32_t)n2*(16*APB) + kt*32);
                mma16816h(acc[2*n2],   a, f[0], f[1]);
                mma16816h(acc[2*n2+1], a, f[2], f[3]);
            }
        }
        #pragma unroll
        for (int j = 0; j < 6; j++) d2a(acc, 2*j, bf2, lane, areg[j]);

        // ---- stage 3: res3(128) = W3 @ [res2; s3]  (KT=8, NT=16) ----
        #pragma unroll
        for (int n = 0; n < 16; n++)
            #pragma unroll
            for (int i = 0; i < 4; i++) acc[n][i] = 0.0f;
        #pragma unroll
        for (int kt = 0; kt < 8; kt++) {
            uint32_t a[4];
            if (kt < 6) { a[0]=areg[kt][0]; a[1]=areg[kt][1]; a[2]=areg[kt][2]; a[3]=areg[kt][3]; }
            else ldsm_x4(a, Abase + kt*32);
            #pragma unroll
            for (int n2 = 0; n2 < 8; n2++) {
                uint32_t f[4];
                ldsm_x4(f, W3a + (uint32_t)n2*(16*APB) + kt*32);
                mma16816h(acc[2*n2],   a, f[0], f[1]);
                mma16816h(acc[2*n2+1], a, f[2], f[3]);
            }
        }
        __syncthreads();   // S2: all A-region reads done; next tile may overwrite

        // ---- epilogue: fgelu(res3+b3)*x, direct sector-aligned global stores ----
        {
            const int p0 = wid*16 + (lane >> 2);
            #pragma unroll
            for (int nt = 0; nt < 16; nt++) {
                int c0 = nt*8 + (lane & 3)*2;
                float b0 = __ldg(&bf3[c0]), b1 = __ldg(&bf3[c0+1]);
                size_t g0i = ((size_t)(b*128 + c0) << 16) + rem;
                size_t g1i = g0i + 65536;
                #pragma unroll
                for (int hrow = 0; hrow < 2; hrow++) {
                    int p = p0 + hrow*8;
                    float e0 = fgelu(acc[nt][2*hrow+0] + b0);
                    float e1 = fgelu(acc[nt][2*hrow+1] + b1);
                    out[g0i + p] = e0 * __ldg(&x[g0i + p]);
                    out[g1i + p] = e1 * __ldg(&x[g1i + p]);
                }
            }
        }
    }
}

// ---------------- launch ----------------
extern "C" void kernel_launch(void* const* d_in, const int* in_sizes, int n_in,
                              void* d_out, int out_size)
{
    const float* x   = (const float*)d_in[0];
    const float* wdw = (const float*)d_in[1];
    const float* bdw = (const float*)d_in[2];
    const float* wf1 = (const float*)d_in[3];
    const float* bf1 = (const float*)d_in[4];
    const float* wf2 = (const float*)d_in[5];
    const float* bf2 = (const float*)d_in[6];
    const float* wf3 = (const float*)d_in[7];
    const float* bf3 = (const float*)d_in[8];
    float* out = (float*)d_out;
    (void)in_sizes; (void)n_in; (void)out_size;

    cudaFuncSetAttribute(fused_mma, cudaFuncAttributeMaxDynamicSharedMemorySize, SMEM_REQ);

    k_prep<<<(64*64 + 96*96 + 128*128 + 255)/256, 256>>>(wf1, wf2, wf3);      // 0
    k_poolh<<<(BB*96*16384 + 255)/256, 256>>>(x);                              // 1
    k_pool2b<<<(BB*CL*4096 + 255)/256, 256>>>();                               // 2
    k_pool4c<<<(BB*CL*1024 + 255)/256, 256>>>();                               // 3
    k_dwall<<<(N_DW0+N_DW1+N_DW2+N_DW3 + 255)/256, 256>>>(x, wdw, bdw);        // 4
    fused_mma<<<4096/TPC, NTHR, SMEM_REQ>>>(x, bf1, bf2, bf3, out);            // 5
}